// round 1
// baseline (speedup 1.0000x reference)
#include <cuda_runtime.h>
#include <math.h>

constexpr int SEQ  = 1576;   // T*N tokens
constexpr int DIM  = 768;
constexpr int NHEAD = 12;
constexpr int HD   = 64;
constexpr int TFR  = 8;      // frames
constexpr int NTOK = 197;    // tokens per frame
constexpr int NPAT = 196;
constexpr int MLPD = 3072;
constexpr int QKVD = 2304;
constexpr float ASCALE = 0.125f;   // 64^-0.5
#define QB 8                 // queries per attention block

// ---------------- scratch (no allocation allowed) ----------------
__device__ float g_p[1568 * 768];
__device__ float g_emb[1568 * 768];
__device__ float g_h[SEQ * DIM];
__device__ float g_a[SEQ * DIM];
__device__ float g_qkv[SEQ * QKVD];
__device__ float g_o[SEQ * DIM];
__device__ float g_mlp[SEQ * MLPD];
__device__ float g_vmean[NHEAD * TFR * HD];

// ---------------- patch extraction: x[1,8,3,224,224] -> P[1568,768] ----------------
__global__ void patch_kernel(const float* __restrict__ x, float* __restrict__ P) {
    int idx = blockIdx.x * blockDim.x + threadIdx.x;
    if (idx >= 1568 * 768) return;
    int m = idx / 768, kcol = idx % 768;
    int t = m / 196, n = m % 196;
    int hp = n / 14, wp = n % 14;
    int c = kcol / 256, rem = kcol % 256;
    int ii = rem / 16, jj = rem % 16;
    P[idx] = x[((t * 3 + c) * 224 + hp * 16 + ii) * 224 + wp * 16 + jj];
}

// ---------------- assemble h with cls token, pos embed, and the reference's axis scramble ----------------
__global__ void assemble_kernel(const float* __restrict__ emb, const float* __restrict__ cls,
                                const float* __restrict__ pos, float* __restrict__ h) {
    int idx = blockIdx.x * blockDim.x + threadIdx.x;
    if (idx >= SEQ * DIM) return;
    int m = idx / DIM, dd = idx % DIM;
    int t = m / NTOK, r = m % NTOK;
    float v;
    if (r == 0) {
        v = cls[dd] + pos[dd];
    } else {
        int pp = r - 1;
        int f = pp * DIM + dd;                 // swapaxes(2,3).reshape bijection
        int n = f % NPAT, dc = f / NPAT;
        v = emb[(t * NPAT + n) * DIM + dc] + pos[(1 + pp) * DIM + dd];
    }
    h[idx] = v;
}

// ---------------- block reduction helper ----------------
__device__ __forceinline__ float block_sum256(float v, float* sh) {
    #pragma unroll
    for (int o = 16; o; o >>= 1) v += __shfl_xor_sync(0xffffffffu, v, o);
    if ((threadIdx.x & 31) == 0) sh[threadIdx.x >> 5] = v;
    __syncthreads();
    float t = 0.f;
    #pragma unroll
    for (int i = 0; i < 8; i++) t += sh[i];
    __syncthreads();
    return t;
}

// ---------------- LayerNorm: one row (768) per block, 256 threads ----------------
__global__ void ln_kernel(const float* __restrict__ x, const float* __restrict__ g,
                          const float* __restrict__ b, float* __restrict__ y) {
    __shared__ float sh[8];
    int row = blockIdx.x, tid = threadIdx.x;
    const float* xr = x + (size_t)row * DIM;
    float v0 = xr[tid], v1 = xr[tid + 256], v2 = xr[tid + 512];
    float mean = block_sum256(v0 + v1 + v2, sh) * (1.f / DIM);
    float d0 = v0 - mean, d1 = v1 - mean, d2 = v2 - mean;
    float var = block_sum256(d0 * d0 + d1 * d1 + d2 * d2, sh) * (1.f / DIM);
    float inv = rsqrtf(var + 1e-5f);
    float* yr = y + (size_t)row * DIM;
    yr[tid]       = d0 * inv * g[tid]       + b[tid];
    yr[tid + 256] = d1 * inv * g[tid + 256] + b[tid + 256];
    yr[tid + 512] = d2 * inv * g[tid + 512] + b[tid + 512];
}

// ---------------- SGEMM: C[M,N] = A[M,K] @ B +bias +residual, optional GELU ----------------
// 64x64 tile, BK=16, 256 threads, 4x4 per thread. TRANSB: B is [N,K] row-major.
template <bool TRANSB>
__global__ void sgemm_kernel(const float* __restrict__ A, const float* __restrict__ B,
                             const float* __restrict__ bias, const float* __restrict__ res,
                             float* __restrict__ C, int M, int N, int K, int act) {
    __shared__ float As[16][64];
    __shared__ float Bs[16][65];
    int tid = threadIdx.x;
    int tx = tid & 15, ty = tid >> 4;
    int row0 = blockIdx.y * 64, col0 = blockIdx.x * 64;
    float acc[4][4] = {};
    for (int k0 = 0; k0 < K; k0 += 16) {
        #pragma unroll 4
        for (int i = tid; i < 64 * 16; i += 256) {
            int m = i >> 4, k = i & 15;
            int gm = row0 + m;
            As[k][m] = (gm < M) ? A[(size_t)gm * K + k0 + k] : 0.f;
        }
        if (TRANSB) {
            #pragma unroll 4
            for (int i = tid; i < 64 * 16; i += 256) {
                int n = i >> 4, k = i & 15;
                int gn = col0 + n;
                Bs[k][n] = (gn < N) ? B[(size_t)gn * K + k0 + k] : 0.f;
            }
        } else {
            #pragma unroll 4
            for (int i = tid; i < 16 * 64; i += 256) {
                int k = i >> 6, n = i & 63;
                int gn = col0 + n;
                Bs[k][n] = (gn < N) ? B[(size_t)(k0 + k) * N + gn] : 0.f;
            }
        }
        __syncthreads();
        #pragma unroll
        for (int k = 0; k < 16; k++) {
            float a[4], bb[4];
            #pragma unroll
            for (int i = 0; i < 4; i++) a[i] = As[k][ty * 4 + i];
            #pragma unroll
            for (int j = 0; j < 4; j++) bb[j] = Bs[k][tx * 4 + j];
            #pragma unroll
            for (int i = 0; i < 4; i++)
                #pragma unroll
                for (int j = 0; j < 4; j++)
                    acc[i][j] = fmaf(a[i], bb[j], acc[i][j]);
        }
        __syncthreads();
    }
    #pragma unroll
    for (int i = 0; i < 4; i++) {
        int gm = row0 + ty * 4 + i;
        if (gm >= M) continue;
        #pragma unroll
        for (int j = 0; j < 4; j++) {
            int gn = col0 + tx * 4 + j;
            if (gn >= N) continue;
            float v = acc[i][j];
            if (bias) v += bias[gn];
            if (res)  v += res[(size_t)gm * N + gn];
            if (act)  v = 0.5f * v * (1.f + erff(v * 0.70710678118f));
            C[(size_t)gm * N + gn] = v;
        }
    }
}

// ---------------- temporal v-mean (attn_t softmax over length-1 axis == identity) ----------------
__global__ void vmean_kernel(const float* __restrict__ qkv, float* __restrict__ vmean) {
    int ht = blockIdx.x;               // h*8 + t
    int h = ht / TFR, t = ht % TFR;
    int d = threadIdx.x;               // 64
    float s = 0.f;
    for (int n = 0; n < NTOK; n++)
        s += qkv[(size_t)(t * NTOK + n) * QKVD + 2 * DIM + h * HD + d];
    vmean[ht * HD + d] = s * (1.f / NTOK);
}

// ---------------- attention: QB queries per block, per-warp softmax ----------------
// joint: numSeg=1, keyLen=SEQ, vmean=null.  spatial: numSeg=8, keyLen=197, +vmean.
__global__ void attn_kernel(const float* __restrict__ qkv, const float* __restrict__ vmean,
                            float* __restrict__ o, int keyLen, int numSeg) {
    extern __shared__ float sm[];
    float* qs  = sm;                      // QB*64
    float* sc  = sm + QB * HD;            // QB*keyLen
    float* red = sc + QB * keyLen;        // 4*QB*64
    __shared__ float wsum[QB];
    int tid = threadIdx.x;
    int hseg = blockIdx.y;
    int h = hseg / numSeg, seg = hseg % numSeg;
    int base = seg * keyLen;
    int q0 = blockIdx.x * QB;
    int nq = min(QB, keyLen - q0);

    for (int i = tid; i < nq * HD; i += 256) {
        int qi = i / HD, d = i % HD;
        qs[qi * HD + d] = qkv[(size_t)(base + q0 + qi) * QKVD + h * HD + d];
    }
    __syncthreads();

    // scores
    for (int kk = tid; kk < keyLen; kk += 256) {
        const float4* kp = (const float4*)(qkv + (size_t)(base + kk) * QKVD + DIM + h * HD);
        float4 k4[16];
        #pragma unroll
        for (int j = 0; j < 16; j++) k4[j] = kp[j];
        for (int qi = 0; qi < nq; qi++) {
            const float4* q4p = (const float4*)(qs + qi * HD);
            float s = 0.f;
            #pragma unroll
            for (int j = 0; j < 16; j++) {
                float4 q4 = q4p[j];
                s += q4.x * k4[j].x + q4.y * k4[j].y + q4.z * k4[j].z + q4.w * k4[j].w;
            }
            sc[qi * keyLen + kk] = s * ASCALE;
        }
    }
    __syncthreads();

    // softmax: warp w handles query w
    int w = tid >> 5, lane = tid & 31;
    if (w < nq) {
        float mx = -1e30f;
        for (int kk = lane; kk < keyLen; kk += 32) mx = fmaxf(mx, sc[w * keyLen + kk]);
        #pragma unroll
        for (int off = 16; off; off >>= 1) mx = fmaxf(mx, __shfl_xor_sync(0xffffffffu, mx, off));
        float sum = 0.f;
        for (int kk = lane; kk < keyLen; kk += 32) {
            float e = __expf(sc[w * keyLen + kk] - mx);
            sc[w * keyLen + kk] = e;
            sum += e;
        }
        #pragma unroll
        for (int off = 16; off; off >>= 1) sum += __shfl_xor_sync(0xffffffffu, sum, off);
        if (lane == 0) wsum[w] = sum;
    }
    __syncthreads();

    // output: 64 dims x 4 key partitions
    int d = tid & 63, part = tid >> 6;
    float acc[QB];
    #pragma unroll
    for (int qi = 0; qi < QB; qi++) acc[qi] = 0.f;
    for (int kk = part; kk < keyLen; kk += 4) {
        float v = qkv[(size_t)(base + kk) * QKVD + 2 * DIM + h * HD + d];
        #pragma unroll
        for (int qi = 0; qi < QB; qi++)
            if (qi < nq) acc[qi] += sc[qi * keyLen + kk] * v;
    }
    #pragma unroll
    for (int qi = 0; qi < QB; qi++)
        red[(part * QB + qi) * HD + d] = acc[qi];
    __syncthreads();
    if (part == 0) {
        for (int qi = 0; qi < nq; qi++) {
            float s = red[qi * HD + d] + red[(QB + qi) * HD + d]
                    + red[(2 * QB + qi) * HD + d] + red[(3 * QB + qi) * HD + d];
            s /= wsum[qi];
            if (vmean) s += vmean[hseg * HD + d];
            o[(size_t)(base + q0 + qi) * DIM + h * HD + d] = s;
        }
    }
}

// ---------------- host ----------------
static void run_sgemm(const float* A, const float* B, const float* bias, const float* res,
                      float* C, int M, int N, int K, int act, bool transb) {
    dim3 grid((N + 63) / 64, (M + 63) / 64);
    if (transb) sgemm_kernel<true ><<<grid, 256>>>(A, B, bias, res, C, M, N, K, act);
    else        sgemm_kernel<false><<<grid, 256>>>(A, B, bias, res, C, M, N, K, act);
}

extern "C" void kernel_launch(void* const* d_in, const int* in_sizes, int n_in,
                              void* d_out, int out_size) {
    const float* x       = (const float*)d_in[0];
    const float* W_patch = (const float*)d_in[1];
    const float* b_patch = (const float*)d_in[2];
    const float* cls     = (const float*)d_in[3];
    const float* pos     = (const float*)d_in[4];
    const float* ln1_g   = (const float*)d_in[5];
    const float* ln1_b   = (const float*)d_in[6];
    const float* qkv_w   = (const float*)d_in[7];
    const float* qkv_b   = (const float*)d_in[8];
    const float* proj_w  = (const float*)d_in[9];
    const float* proj_b  = (const float*)d_in[10];
    const float* ln2_g   = (const float*)d_in[11];
    const float* ln2_b   = (const float*)d_in[12];
    const float* fc1_w   = (const float*)d_in[13];
    const float* fc1_b   = (const float*)d_in[14];
    const float* fc2_w   = (const float*)d_in[15];
    const float* fc2_b   = (const float*)d_in[16];
    const float* lnf_g   = (const float*)d_in[17];
    const float* lnf_b   = (const float*)d_in[18];

    float *p_, *emb_, *h_, *a_, *qkv_, *o_, *mlp_, *vm_;
    cudaGetSymbolAddress((void**)&p_,   g_p);
    cudaGetSymbolAddress((void**)&emb_, g_emb);
    cudaGetSymbolAddress((void**)&h_,   g_h);
    cudaGetSymbolAddress((void**)&a_,   g_a);
    cudaGetSymbolAddress((void**)&qkv_, g_qkv);
    cudaGetSymbolAddress((void**)&o_,   g_o);
    cudaGetSymbolAddress((void**)&mlp_, g_mlp);
    cudaGetSymbolAddress((void**)&vm_,  g_vmean);

    size_t smem_joint = (size_t)(QB * HD + QB * SEQ  + 4 * QB * HD) * sizeof(float); // ~60.7KB
    size_t smem_sp    = (size_t)(QB * HD + QB * NTOK + 4 * QB * HD) * sizeof(float);
    cudaFuncSetAttribute(attn_kernel, cudaFuncAttributeMaxDynamicSharedMemorySize, (int)smem_joint);

    // patch embed + assembly
    patch_kernel<<<(1568 * 768 + 255) / 256, 256>>>(x, p_);
    run_sgemm(p_, W_patch, b_patch, nullptr, emb_, 1568, 768, 768, 0, true);
    assemble_kernel<<<(SEQ * DIM + 255) / 256, 256>>>(emb_, cls, pos, h_);

    for (int i = 0; i < 12; i++) {
        // attention block
        ln_kernel<<<SEQ, 256>>>(h_, ln1_g + i * DIM, ln1_b + i * DIM, a_);
        run_sgemm(a_, qkv_w + (size_t)i * DIM * QKVD, qkv_b + i * QKVD, nullptr,
                  qkv_, SEQ, QKVD, DIM, 0, false);
        if ((i & 1) == 0) {
            // divided space-time: temporal branch == mean over tokens (softmax of 1x1 == 1)
            vmean_kernel<<<NHEAD * TFR, HD>>>(qkv_, vm_);
            dim3 g((NTOK + QB - 1) / QB, NHEAD * TFR);
            attn_kernel<<<g, 256, smem_sp>>>(qkv_, vm_, o_, NTOK, TFR);
        } else {
            dim3 g(SEQ / QB, NHEAD);
            attn_kernel<<<g, 256, smem_joint>>>(qkv_, nullptr, o_, SEQ, 1);
        }
        run_sgemm(o_, proj_w + (size_t)i * DIM * DIM, proj_b + i * DIM, h_,
                  h_, SEQ, DIM, DIM, 0, false);
        // mlp block
        ln_kernel<<<SEQ, 256>>>(h_, ln2_g + i * DIM, ln2_b + i * DIM, a_);
        run_sgemm(a_, fc1_w + (size_t)i * DIM * MLPD, fc1_b + i * MLPD, nullptr,
                  mlp_, SEQ, MLPD, DIM, 1, false);
        run_sgemm(mlp_, fc2_w + (size_t)i * MLPD * DIM, fc2_b + i * DIM, h_,
                  h_, SEQ, DIM, MLPD, 0, false);
    }

    ln_kernel<<<SEQ, 256>>>(h_, lnf_g, lnf_b, (float*)d_out);
}

// round 3
// speedup vs baseline: 2.1800x; 2.1800x over previous
#include <cuda_runtime.h>
#include <cuda_bf16.h>
#include <math.h>
#include <stdint.h>

constexpr int SEQ  = 1576;   // T*N tokens
constexpr int DIM  = 768;
constexpr int NHEAD = 12;
constexpr int HD   = 64;
constexpr int TFR  = 8;      // frames
constexpr int NTOK = 197;    // tokens per frame
constexpr int NPAT = 196;
constexpr int MLPD = 3072;
constexpr int QKVD = 2304;
constexpr float ASCALE = 0.125f;   // 64^-0.5
#define QB 8                 // queries per attention block

// ---------------- scratch (no allocation allowed) ----------------
__device__ float g_p[1568 * 768];
__device__ float g_emb[1568 * 768];
__device__ float g_h[SEQ * DIM];
__device__ float g_a[SEQ * DIM];
__device__ float g_qkv[SEQ * QKVD];
__device__ float g_o[SEQ * DIM];
__device__ float g_mlp[SEQ * MLPD];
__device__ float g_vmean[NHEAD * TFR * HD];
// transposed weights: [N, K] K-major
__device__ float g_qkvT[12 * QKVD * DIM];
__device__ float g_projT[12 * DIM * DIM];
__device__ float g_fc1T[12 * MLPD * DIM];
__device__ float g_fc2T[12 * DIM * MLPD];

// ================= helpers =================
__device__ __forceinline__ uint32_t smem_u32(const void* p) {
    uint32_t a;
    asm("{ .reg .u64 t; cvta.to.shared.u64 t, %1; cvt.u32.u64 %0, t; }" : "=r"(a) : "l"(p));
    return a;
}

#define LDM4(r, addr) \
    asm volatile("ldmatrix.sync.aligned.m8n8.x4.shared.b16 {%0,%1,%2,%3}, [%4];" \
        : "=r"((r)[0]), "=r"((r)[1]), "=r"((r)[2]), "=r"((r)[3]) : "r"(addr))

#define MMA_BF16(c, a, b0, b1) \
    asm volatile("mma.sync.aligned.m16n8k16.row.col.f32.bf16.bf16.f32 " \
        "{%0,%1,%2,%3}, {%4,%5,%6,%7}, {%8,%9}, {%0,%1,%2,%3};" \
        : "+f"((c)[0]), "+f"((c)[1]), "+f"((c)[2]), "+f"((c)[3]) \
        : "r"((a)[0]), "r"((a)[1]), "r"((a)[2]), "r"((a)[3]), "r"(b0), "r"(b1))

// split fp32 -> bf16 hi + bf16 lo (packed pairs)
__device__ __forceinline__ void split4(float4 v, uint32_t* hi, uint32_t* lo) {
    __nv_bfloat16 h0 = __float2bfloat16(v.x), h1 = __float2bfloat16(v.y);
    __nv_bfloat16 h2 = __float2bfloat16(v.z), h3 = __float2bfloat16(v.w);
    __nv_bfloat16 l0 = __float2bfloat16(v.x - __bfloat162float(h0));
    __nv_bfloat16 l1 = __float2bfloat16(v.y - __bfloat162float(h1));
    __nv_bfloat16 l2 = __float2bfloat16(v.z - __bfloat162float(h2));
    __nv_bfloat16 l3 = __float2bfloat16(v.w - __bfloat162float(h3));
    hi[0] = (uint32_t)__bfloat16_as_ushort(h0) | ((uint32_t)__bfloat16_as_ushort(h1) << 16);
    hi[1] = (uint32_t)__bfloat16_as_ushort(h2) | ((uint32_t)__bfloat16_as_ushort(h3) << 16);
    lo[0] = (uint32_t)__bfloat16_as_ushort(l0) | ((uint32_t)__bfloat16_as_ushort(l1) << 16);
    lo[1] = (uint32_t)__bfloat16_as_ushort(l2) | ((uint32_t)__bfloat16_as_ushort(l3) << 16);
}

// ---------------- weight transpose: [K,N] -> [N,K], per-layer grid.z ----------------
__global__ void transpose_kernel(const float* __restrict__ in, float* __restrict__ out,
                                 int K, int N) {
    __shared__ float t[32][33];
    size_t base = (size_t)blockIdx.z * K * N;
    int n0 = blockIdx.x * 32, k0 = blockIdx.y * 32;
    int tx = threadIdx.x, ty = threadIdx.y;
    #pragma unroll
    for (int j = 0; j < 32; j += 8)
        t[ty + j][tx] = in[base + (size_t)(k0 + ty + j) * N + n0 + tx];
    __syncthreads();
    #pragma unroll
    for (int j = 0; j < 32; j += 8)
        out[base + (size_t)(n0 + ty + j) * K + k0 + tx] = t[tx][ty + j];
}

// ===================================================================================
// bf16x3 MMA GEMM: C[M,N] = A[M,K] @ B[N,K]^T (+bias, +res, optional exact GELU)
// CTA tile 64x128, BK=32, 8 warps (warp tile 32x32), double-buffered smem.
// A = Ahi + Alo (bf16 split); C = Ahi*Bhi + Ahi*Blo + Alo*Bhi  (fp32-class accuracy)
// ===================================================================================
constexpr int RS = 80;                // smem row stride bytes (32 bf16 + pad) -> conflict-free ldmatrix
constexpr int AH_OFF = 0;             // 64 * 80
constexpr int AL_OFF = 5120;
constexpr int BH_OFF = 10240;         // 128 * 80
constexpr int BL_OFF = 20480;
constexpr int STAGE  = 30720;

__global__ void __launch_bounds__(256) mma_gemm(const float* __restrict__ A,
        const float* __restrict__ B, const float* __restrict__ bias,
        const float* __restrict__ res, float* __restrict__ C,
        int M, int N, int K, int act) {
    extern __shared__ __align__(1024) char sm[];
    const int tid = threadIdx.x;
    const int lane = tid & 31, wid = tid >> 5;
    const int wm = wid & 1, wn = wid >> 1;
    const int row0 = blockIdx.y * 64, col0 = blockIdx.x * 128;
    const uint32_t smb = smem_u32(sm);

    // ldmatrix per-lane source row/col offsets
    const int a_row = ((lane >> 3) & 1) * 8 + (lane & 7);
    const int a_kb  = (lane >> 4) * 16;          // byte offset within k (8 bf16 = 16B)
    const int b_row = (lane >> 4) * 8 + (lane & 7);
    const int b_kb  = ((lane >> 3) & 1) * 16;

    // per-thread ldg/sts indices
    const int am  = tid >> 3;          // A tile rows handled: am, am+32? no: r loop
    const int ak4 = tid & 7;

    float c[2][4][4];
    #pragma unroll
    for (int i = 0; i < 2; i++)
        #pragma unroll
        for (int j = 0; j < 4; j++)
            #pragma unroll
            for (int k = 0; k < 4; k++) c[i][j][k] = 0.f;

    const int nk = K >> 5;
    float4 ra[2], rb[4];

    // ---- prologue: load tile 0 ----
    #pragma unroll
    for (int r = 0; r < 2; r++) {
        int m = am + r * 32;
        int gm = row0 + m;
        ra[r] = (gm < M) ? *(const float4*)(A + (size_t)gm * K + ak4 * 4)
                         : make_float4(0.f, 0.f, 0.f, 0.f);
    }
    #pragma unroll
    for (int r = 0; r < 4; r++) {
        int n = am + r * 32;
        rb[r] = *(const float4*)(B + (size_t)(col0 + n) * K + ak4 * 4);
    }
    {
        char* st = sm;
        #pragma unroll
        for (int r = 0; r < 2; r++) {
            int m = am + r * 32;
            uint32_t hi[2], lo[2];
            split4(ra[r], hi, lo);
            *(uint2*)(st + AH_OFF + m * RS + ak4 * 8) = make_uint2(hi[0], hi[1]);
            *(uint2*)(st + AL_OFF + m * RS + ak4 * 8) = make_uint2(lo[0], lo[1]);
        }
        #pragma unroll
        for (int r = 0; r < 4; r++) {
            int n = am + r * 32;
            uint32_t hi[2], lo[2];
            split4(rb[r], hi, lo);
            *(uint2*)(st + BH_OFF + n * RS + ak4 * 8) = make_uint2(hi[0], hi[1]);
            *(uint2*)(st + BL_OFF + n * RS + ak4 * 8) = make_uint2(lo[0], lo[1]);
        }
    }
    __syncthreads();

    for (int it = 0; it < nk; it++) {
        // prefetch next tile to regs
        if (it + 1 < nk) {
            int k0 = (it + 1) << 5;
            #pragma unroll
            for (int r = 0; r < 2; r++) {
                int m = am + r * 32;
                int gm = row0 + m;
                ra[r] = (gm < M) ? *(const float4*)(A + (size_t)gm * K + k0 + ak4 * 4)
                                 : make_float4(0.f, 0.f, 0.f, 0.f);
            }
            #pragma unroll
            for (int r = 0; r < 4; r++) {
                int n = am + r * 32;
                rb[r] = *(const float4*)(B + (size_t)(col0 + n) * K + k0 + ak4 * 4);
            }
        }

        // compute on stage it&1
        uint32_t sb = smb + (uint32_t)(it & 1) * STAGE;
        #pragma unroll
        for (int kk = 0; kk < 2; kk++) {
            uint32_t bh[8], bl[8];
            #pragma unroll
            for (int nip = 0; nip < 2; nip++) {
                uint32_t baddr = sb + BH_OFF + (wn * 32 + nip * 16 + b_row) * RS + b_kb + kk * 32;
                LDM4(&bh[nip * 4], baddr);
                LDM4(&bl[nip * 4], baddr + (BL_OFF - BH_OFF));
            }
            #pragma unroll
            for (int mi = 0; mi < 2; mi++) {
                uint32_t ah[4], al[4];
                uint32_t aaddr = sb + AH_OFF + (wm * 32 + mi * 16 + a_row) * RS + a_kb + kk * 32;
                LDM4(ah, aaddr);
                LDM4(al, aaddr + (AL_OFF - AH_OFF));
                #pragma unroll
                for (int ni = 0; ni < 4; ni++) {
                    uint32_t b0h = bh[(ni >> 1) * 4 + (ni & 1) * 2];
                    uint32_t b1h = bh[(ni >> 1) * 4 + (ni & 1) * 2 + 1];
                    uint32_t b0l = bl[(ni >> 1) * 4 + (ni & 1) * 2];
                    uint32_t b1l = bl[(ni >> 1) * 4 + (ni & 1) * 2 + 1];
                    MMA_BF16(c[mi][ni], ah, b0h, b1h);
                    MMA_BF16(c[mi][ni], ah, b0l, b1l);
                    MMA_BF16(c[mi][ni], al, b0h, b1h);
                }
            }
        }
        __syncthreads();

        // store next tile to the other stage
        if (it + 1 < nk) {
            char* st = sm + ((it + 1) & 1) * STAGE;
            #pragma unroll
            for (int r = 0; r < 2; r++) {
                int m = am + r * 32;
                uint32_t hi[2], lo[2];
                split4(ra[r], hi, lo);
                *(uint2*)(st + AH_OFF + m * RS + ak4 * 8) = make_uint2(hi[0], hi[1]);
                *(uint2*)(st + AL_OFF + m * RS + ak4 * 8) = make_uint2(lo[0], lo[1]);
            }
            #pragma unroll
            for (int r = 0; r < 4; r++) {
                int n = am + r * 32;
                uint32_t hi[2], lo[2];
                split4(rb[r], hi, lo);
                *(uint2*)(st + BH_OFF + n * RS + ak4 * 8) = make_uint2(hi[0], hi[1]);
                *(uint2*)(st + BL_OFF + n * RS + ak4 * 8) = make_uint2(lo[0], lo[1]);
            }
            __syncthreads();
        }
    }

    // ---- epilogue ----
    const int g = lane >> 2, t = lane & 3;
    #pragma unroll
    for (int mi = 0; mi < 2; mi++) {
        #pragma unroll
        for (int ni = 0; ni < 4; ni++) {
            int col = col0 + wn * 32 + ni * 8 + t * 2;
            float2 bb = bias ? *(const float2*)(bias + col) : make_float2(0.f, 0.f);
            #pragma unroll
            for (int half = 0; half < 2; half++) {
                int gm = row0 + wm * 32 + mi * 16 + g + half * 8;
                if (gm >= M) continue;
                float v0 = c[mi][ni][half * 2 + 0] + bb.x;
                float v1 = c[mi][ni][half * 2 + 1] + bb.y;
                if (act) {
                    v0 = 0.5f * v0 * (1.f + erff(v0 * 0.70710678118f));
                    v1 = 0.5f * v1 * (1.f + erff(v1 * 0.70710678118f));
                }
                if (res) {
                    float2 rv = *(const float2*)(res + (size_t)gm * N + col);
                    v0 += rv.x; v1 += rv.y;
                }
                *(float2*)(C + (size_t)gm * N + col) = make_float2(v0, v1);
            }
        }
    }
}

// ---------------- patch extraction ----------------
__global__ void patch_kernel(const float* __restrict__ x, float* __restrict__ P) {
    int idx = blockIdx.x * blockDim.x + threadIdx.x;
    if (idx >= 1568 * 768) return;
    int m = idx / 768, kcol = idx % 768;
    int t = m / 196, n = m % 196;
    int hp = n / 14, wp = n % 14;
    int c = kcol / 256, rem = kcol % 256;
    int ii = rem / 16, jj = rem % 16;
    P[idx] = x[((t * 3 + c) * 224 + hp * 16 + ii) * 224 + wp * 16 + jj];
}

// ---------------- assemble h ----------------
__global__ void assemble_kernel(const float* __restrict__ emb, const float* __restrict__ cls,
                                const float* __restrict__ pos, float* __restrict__ h) {
    int idx = blockIdx.x * blockDim.x + threadIdx.x;
    if (idx >= SEQ * DIM) return;
    int m = idx / DIM, dd = idx % DIM;
    int t = m / NTOK, r = m % NTOK;
    float v;
    if (r == 0) {
        v = cls[dd] + pos[dd];
    } else {
        int pp = r - 1;
        int f = pp * DIM + dd;
        int n = f % NPAT, dc = f / NPAT;
        v = emb[(t * NPAT + n) * DIM + dc] + pos[(1 + pp) * DIM + dd];
    }
    h[idx] = v;
}

// ---------------- block reduction ----------------
__device__ __forceinline__ float block_sum256(float v, float* sh) {
    #pragma unroll
    for (int o = 16; o; o >>= 1) v += __shfl_xor_sync(0xffffffffu, v, o);
    if ((threadIdx.x & 31) == 0) sh[threadIdx.x >> 5] = v;
    __syncthreads();
    float t = 0.f;
    #pragma unroll
    for (int i = 0; i < 8; i++) t += sh[i];
    __syncthreads();
    return t;
}

// ---------------- LayerNorm ----------------
__global__ void ln_kernel(const float* __restrict__ x, const float* __restrict__ g,
                          const float* __restrict__ b, float* __restrict__ y) {
    __shared__ float sh[8];
    int row = blockIdx.x, tid = threadIdx.x;
    const float* xr = x + (size_t)row * DIM;
    float v0 = xr[tid], v1 = xr[tid + 256], v2 = xr[tid + 512];
    float mean = block_sum256(v0 + v1 + v2, sh) * (1.f / DIM);
    float d0 = v0 - mean, d1 = v1 - mean, d2 = v2 - mean;
    float var = block_sum256(d0 * d0 + d1 * d1 + d2 * d2, sh) * (1.f / DIM);
    float inv = rsqrtf(var + 1e-5f);
    float* yr = y + (size_t)row * DIM;
    yr[tid]       = d0 * inv * g[tid]       + b[tid];
    yr[tid + 256] = d1 * inv * g[tid + 256] + b[tid + 256];
    yr[tid + 512] = d2 * inv * g[tid + 512] + b[tid + 512];
}

// ---------------- temporal v-mean ----------------
__global__ void vmean_kernel(const float* __restrict__ qkv, float* __restrict__ vmean) {
    int ht = blockIdx.x;
    int t = ht % TFR, h = ht / TFR;
    int d = threadIdx.x;
    float s = 0.f;
    for (int n = 0; n < NTOK; n++)
        s += qkv[(size_t)(t * NTOK + n) * QKVD + 2 * DIM + h * HD + d];
    vmean[ht * HD + d] = s * (1.f / NTOK);
}

// ---------------- attention ----------------
__global__ void attn_kernel(const float* __restrict__ qkv, const float* __restrict__ vmean,
                            float* __restrict__ o, int keyLen, int numSeg) {
    extern __shared__ float smf[];
    float* qs  = smf;
    float* sc  = smf + QB * HD;
    float* red = sc + QB * keyLen;
    __shared__ float wsum[QB];
    int tid = threadIdx.x;
    int hseg = blockIdx.y;
    int h = hseg / numSeg, seg = hseg % numSeg;
    int base = seg * keyLen;
    int q0 = blockIdx.x * QB;
    int nq = min(QB, keyLen - q0);

    for (int i = tid; i < nq * HD; i += 256) {
        int qi = i / HD, d = i % HD;
        qs[qi * HD + d] = qkv[(size_t)(base + q0 + qi) * QKVD + h * HD + d];
    }
    __syncthreads();

    for (int kk = tid; kk < keyLen; kk += 256) {
        const float4* kp = (const float4*)(qkv + (size_t)(base + kk) * QKVD + DIM + h * HD);
        float4 k4[16];
        #pragma unroll
        for (int j = 0; j < 16; j++) k4[j] = kp[j];
        for (int qi = 0; qi < nq; qi++) {
            const float4* q4p = (const float4*)(qs + qi * HD);
            float s = 0.f;
            #pragma unroll
            for (int j = 0; j < 16; j++) {
                float4 q4 = q4p[j];
                s += q4.x * k4[j].x + q4.y * k4[j].y + q4.z * k4[j].z + q4.w * k4[j].w;
            }
            sc[qi * keyLen + kk] = s * ASCALE;
        }
    }
    __syncthreads();

    int w = tid >> 5, lane = tid & 31;
    if (w < nq) {
        float mx = -1e30f;
        for (int kk = lane; kk < keyLen; kk += 32) mx = fmaxf(mx, sc[w * keyLen + kk]);
        #pragma unroll
        for (int off = 16; off; off >>= 1) mx = fmaxf(mx, __shfl_xor_sync(0xffffffffu, mx, off));
        float sum = 0.f;
        for (int kk = lane; kk < keyLen; kk += 32) {
            float e = __expf(sc[w * keyLen + kk] - mx);
            sc[w * keyLen + kk] = e;
            sum += e;
        }
        #pragma unroll
        for (int off = 16; off; off >>= 1) sum += __shfl_xor_sync(0xffffffffu, sum, off);
        if (lane == 0) wsum[w] = sum;
    }
    __syncthreads();

    int d = tid & 63, part = tid >> 6;
    float acc[QB];
    #pragma unroll
    for (int qi = 0; qi < QB; qi++) acc[qi] = 0.f;
    for (int kk = part; kk < keyLen; kk += 4) {
        float v = qkv[(size_t)(base + kk) * QKVD + 2 * DIM + h * HD + d];
        #pragma unroll
        for (int qi = 0; qi < QB; qi++)
            if (qi < nq) acc[qi] += sc[qi * keyLen + kk] * v;
    }
    #pragma unroll
    for (int qi = 0; qi < QB; qi++)
        red[(part * QB + qi) * HD + d] = acc[qi];
    __syncthreads();
    if (part == 0) {
        for (int qi = 0; qi < nq; qi++) {
            float s = red[qi * HD + d] + red[(QB + qi) * HD + d]
                    + red[(2 * QB + qi) * HD + d] + red[(3 * QB + qi) * HD + d];
            s /= wsum[qi];
            if (vmean) s += vmean[hseg * HD + d];
            o[(size_t)(base + q0 + qi) * DIM + h * HD + d] = s;
        }
    }
}

// ---------------- host ----------------
static void run_mma(const float* A, const float* B, const float* bias, const float* res,
                    float* C, int M, int N, int K, int act) {
    dim3 grid(N / 128, (M + 63) / 64);
    mma_gemm<<<grid, 256, 2 * STAGE>>>(A, B, bias, res, C, M, N, K, act);
}

extern "C" void kernel_launch(void* const* d_in, const int* in_sizes, int n_in,
                              void* d_out, int out_size) {
    const float* x       = (const float*)d_in[0];
    const float* W_patch = (const float*)d_in[1];
    const float* b_patch = (const float*)d_in[2];
    const float* cls     = (const float*)d_in[3];
    const float* pos     = (const float*)d_in[4];
    const float* ln1_g   = (const float*)d_in[5];
    const float* ln1_b   = (const float*)d_in[6];
    const float* qkv_w   = (const float*)d_in[7];
    const float* qkv_b   = (const float*)d_in[8];
    const float* proj_w  = (const float*)d_in[9];
    const float* proj_b  = (const float*)d_in[10];
    const float* ln2_g   = (const float*)d_in[11];
    const float* ln2_b   = (const float*)d_in[12];
    const float* fc1_w   = (const float*)d_in[13];
    const float* fc1_b   = (const float*)d_in[14];
    const float* fc2_w   = (const float*)d_in[15];
    const float* fc2_b   = (const float*)d_in[16];
    const float* lnf_g   = (const float*)d_in[17];
    const float* lnf_b   = (const float*)d_in[18];

    float *p_, *emb_, *h_, *a_, *qkv_, *o_, *mlp_, *vm_;
    float *qkvT, *projT, *fc1T, *fc2T;
    cudaGetSymbolAddress((void**)&p_,   g_p);
    cudaGetSymbolAddress((void**)&emb_, g_emb);
    cudaGetSymbolAddress((void**)&h_,   g_h);
    cudaGetSymbolAddress((void**)&a_,   g_a);
    cudaGetSymbolAddress((void**)&qkv_, g_qkv);
    cudaGetSymbolAddress((void**)&o_,   g_o);
    cudaGetSymbolAddress((void**)&mlp_, g_mlp);
    cudaGetSymbolAddress((void**)&vm_,  g_vmean);
    cudaGetSymbolAddress((void**)&qkvT, g_qkvT);
    cudaGetSymbolAddress((void**)&projT, g_projT);
    cudaGetSymbolAddress((void**)&fc1T, g_fc1T);
    cudaGetSymbolAddress((void**)&fc2T, g_fc2T);

    cudaFuncSetAttribute(mma_gemm, cudaFuncAttributeMaxDynamicSharedMemorySize, 2 * STAGE);

    size_t smem_joint = (size_t)(QB * HD + QB * SEQ  + 4 * QB * HD) * sizeof(float);
    size_t smem_sp    = (size_t)(QB * HD + QB * NTOK + 4 * QB * HD) * sizeof(float);
    cudaFuncSetAttribute(attn_kernel, cudaFuncAttributeMaxDynamicSharedMemorySize, (int)smem_joint);

    // transpose weights -> [N, K]
    dim3 tb(32, 8);
    transpose_kernel<<<dim3(QKVD / 32, DIM / 32, 12), tb>>>(qkv_w,  qkvT, DIM, QKVD);
    transpose_kernel<<<dim3(DIM / 32,  DIM / 32, 12), tb>>>(proj_w, projT, DIM, DIM);
    transpose_kernel<<<dim3(MLPD / 32, DIM / 32, 12), tb>>>(fc1_w,  fc1T, DIM, MLPD);
    transpose_kernel<<<dim3(DIM / 32, MLPD / 32, 12), tb>>>(fc2_w,  fc2T, MLPD, DIM);

    // patch embed + assembly (W_patch already [N,K])
    patch_kernel<<<(1568 * 768 + 255) / 256, 256>>>(x, p_);
    run_mma(p_, W_patch, b_patch, nullptr, emb_, 1568, 768, 768, 0);
    assemble_kernel<<<(SEQ * DIM + 255) / 256, 256>>>(emb_, cls, pos, h_);

    for (int i = 0; i < 12; i++) {
        ln_kernel<<<SEQ, 256>>>(h_, ln1_g + i * DIM, ln1_b + i * DIM, a_);
        run_mma(a_, qkvT + (size_t)i * QKVD * DIM, qkv_b + i * QKVD, nullptr,
                qkv_, SEQ, QKVD, DIM, 0);
        if ((i & 1) == 0) {
            vmean_kernel<<<NHEAD * TFR, HD>>>(qkv_, vm_);
            dim3 g((NTOK + QB - 1) / QB, NHEAD * TFR);
            attn_kernel<<<g, 256, smem_sp>>>(qkv_, vm_, o_, NTOK, TFR);
        } else {
            dim3 g(SEQ / QB, NHEAD);
            attn_kernel<<<g, 256, smem_joint>>>(qkv_, nullptr, o_, SEQ, 1);
        }
        run_mma(o_, projT + (size_t)i * DIM * DIM, proj_b + i * DIM, h_,
                h_, SEQ, DIM, DIM, 0);
        ln_kernel<<<SEQ, 256>>>(h_, ln2_g + i * DIM, ln2_b + i * DIM, a_);
        run_mma(a_, fc1T + (size_t)i * MLPD * DIM, fc1_b + i * MLPD, nullptr,
                mlp_, SEQ, MLPD, DIM, 1);
        run_mma(mlp_, fc2T + (size_t)i * DIM * MLPD, fc2_b + i * DIM, h_,
                h_, SEQ, DIM, MLPD, 0);
    }

    ln_kernel<<<SEQ, 256>>>(h_, lnf_g, lnf_b, (float*)d_out);
}

// round 4
// speedup vs baseline: 2.3939x; 1.0981x over previous
#include <cuda_runtime.h>
#include <cuda_bf16.h>
#include <math.h>
#include <stdint.h>

constexpr int SEQ  = 1576;   // T*N tokens
constexpr int DIM  = 768;
constexpr int NHEAD = 12;
constexpr int HD   = 64;
constexpr int TFR  = 8;      // frames
constexpr int NTOK = 197;    // tokens per frame
constexpr int NPAT = 196;
constexpr int MLPD = 3072;
constexpr int QKVD = 2304;
constexpr float ASCALE = 0.125f;
#define QB 8

// ---------------- scratch (no allocation allowed) ----------------
__device__ float g_emb[1568 * 768];
__device__ float g_h[SEQ * DIM];
__device__ float g_qkv[SEQ * QKVD];
__device__ float g_vmean[NHEAD * TFR * HD];
// bf16 hi/lo activation buffers
__device__ unsigned short g_p_hi[1568 * 768],  g_p_lo[1568 * 768];
__device__ unsigned short g_a_hi[SEQ * DIM],   g_a_lo[SEQ * DIM];
__device__ unsigned short g_o_hi[SEQ * DIM],   g_o_lo[SEQ * DIM];
__device__ unsigned short g_m_hi[SEQ * MLPD],  g_m_lo[SEQ * MLPD];
// bf16 hi/lo weights, [N,K] K-major
__device__ unsigned short g_wp_hi[DIM * DIM],        g_wp_lo[DIM * DIM];
__device__ unsigned short g_qkvT_hi[12 * QKVD * DIM], g_qkvT_lo[12 * QKVD * DIM];
__device__ unsigned short g_projT_hi[12 * DIM * DIM], g_projT_lo[12 * DIM * DIM];
__device__ unsigned short g_fc1T_hi[12 * MLPD * DIM], g_fc1T_lo[12 * MLPD * DIM];
__device__ unsigned short g_fc2T_hi[12 * DIM * MLPD], g_fc2T_lo[12 * DIM * MLPD];

// ================= helpers =================
__device__ __forceinline__ uint32_t smem_u32(const void* p) {
    uint32_t a;
    asm("{ .reg .u64 t; cvta.to.shared.u64 t, %1; cvt.u32.u64 %0, t; }" : "=r"(a) : "l"(p));
    return a;
}
__device__ __forceinline__ void split1(float v, unsigned short& hi, unsigned short& lo) {
    __nv_bfloat16 h = __float2bfloat16(v);
    __nv_bfloat16 l = __float2bfloat16(v - __bfloat162float(h));
    hi = __bfloat16_as_ushort(h);
    lo = __bfloat16_as_ushort(l);
}

#define LDM4(r, addr) \
    asm volatile("ldmatrix.sync.aligned.m8n8.x4.shared.b16 {%0,%1,%2,%3}, [%4];" \
        : "=r"((r)[0]), "=r"((r)[1]), "=r"((r)[2]), "=r"((r)[3]) : "r"(addr))

#define MMA_BF16(c, a, b0, b1) \
    asm volatile("mma.sync.aligned.m16n8k16.row.col.f32.bf16.bf16.f32 " \
        "{%0,%1,%2,%3}, {%4,%5,%6,%7}, {%8,%9}, {%0,%1,%2,%3};" \
        : "+f"((c)[0]), "+f"((c)[1]), "+f"((c)[2]), "+f"((c)[3]) \
        : "r"((a)[0]), "r"((a)[1]), "r"((a)[2]), "r"((a)[3]), "r"(b0), "r"(b1))

#define CPA16(dst, src, sz) \
    asm volatile("cp.async.cg.shared.global [%0], [%1], 16, %2;" \
        :: "r"(dst), "l"(src), "r"(sz))
#define CPA_COMMIT() asm volatile("cp.async.commit_group;")
#define CPA_WAIT1()  asm volatile("cp.async.wait_group 1;")

// ---------------- transpose + split: fp32 [K,N] -> bf16 hi/lo [N,K], per-layer z ----------------
__global__ void transpose_split_kernel(const float* __restrict__ in,
        unsigned short* __restrict__ ohi, unsigned short* __restrict__ olo, int K, int N) {
    __shared__ float t[32][33];
    size_t base = (size_t)blockIdx.z * K * N;
    int n0 = blockIdx.x * 32, k0 = blockIdx.y * 32;
    int tx = threadIdx.x, ty = threadIdx.y;
    #pragma unroll
    for (int j = 0; j < 32; j += 8)
        t[ty + j][tx] = in[base + (size_t)(k0 + ty + j) * N + n0 + tx];
    __syncthreads();
    #pragma unroll
    for (int j = 0; j < 32; j += 8) {
        unsigned short hi, lo;
        split1(t[tx][ty + j], hi, lo);
        size_t o = base + (size_t)(n0 + ty + j) * K + k0 + tx;
        ohi[o] = hi; olo[o] = lo;
    }
}

// ---------------- elementwise split (W_patch, already [N,K]) ----------------
__global__ void split_kernel(const float* __restrict__ in,
        unsigned short* __restrict__ hi, unsigned short* __restrict__ lo, int n) {
    int i = blockIdx.x * blockDim.x + threadIdx.x;
    if (i >= n) return;
    split1(in[i], hi[i], lo[i]);
}

// ===================================================================================
// bf16x3 MMA GEMM, cp.async 3-stage pipeline.
// C[M,N] = A[M,K] @ B[N,K]^T (+bias, +res, GELU); output fp32 OR bf16 hi/lo split.
// CTA tile 64x128, BK=32, 8 warps (warp tile 32x32).
// ===================================================================================
constexpr int RS = 80;
constexpr int AH_OFF = 0;
constexpr int AL_OFF = 5120;
constexpr int BH_OFF = 10240;
constexpr int BL_OFF = 20480;
constexpr int STAGE  = 30720;
constexpr int NSTG   = 3;

__device__ __forceinline__ void load_stage(uint32_t sb,
        const unsigned short* __restrict__ Ahi, const unsigned short* __restrict__ Alo,
        const unsigned short* __restrict__ Bhi, const unsigned short* __restrict__ Blo,
        int row0, int col0, int K, int k0, int M, int tid) {
    int r = tid >> 2, ch = tid & 3;
    uint32_t doff = (uint32_t)(r * RS + ch * 16);
    size_t asrc = (size_t)(row0 + r) * K + k0 + ch * 8;
    int av = (row0 + r < M) ? 16 : 0;
    CPA16(sb + AH_OFF + doff, Ahi + asrc, av);
    CPA16(sb + AL_OFF + doff, Alo + asrc, av);
    size_t b0 = (size_t)(col0 + r) * K + k0 + ch * 8;
    size_t b1 = (size_t)(col0 + 64 + r) * K + k0 + ch * 8;
    CPA16(sb + BH_OFF + doff, Bhi + b0, 16);
    CPA16(sb + BH_OFF + doff + 64 * RS, Bhi + b1, 16);
    CPA16(sb + BL_OFF + doff, Blo + b0, 16);
    CPA16(sb + BL_OFF + doff + 64 * RS, Blo + b1, 16);
    CPA_COMMIT();
}

__global__ void __launch_bounds__(256, 2) mma_gemm(
        const unsigned short* __restrict__ Ahi, const unsigned short* __restrict__ Alo,
        const unsigned short* __restrict__ Bhi, const unsigned short* __restrict__ Blo,
        const float* __restrict__ bias, const float* __restrict__ res,
        float* __restrict__ C, unsigned short* __restrict__ Chi,
        unsigned short* __restrict__ Clo,
        int M, int N, int K, int act) {
    extern __shared__ __align__(128) char sm[];
    const int tid = threadIdx.x;
    const int lane = tid & 31, wid = tid >> 5;
    const int wm = wid & 1, wn = wid >> 1;
    const int row0 = blockIdx.y * 64, col0 = blockIdx.x * 128;
    const uint32_t smb = smem_u32(sm);

    const int a_row = ((lane >> 3) & 1) * 8 + (lane & 7);
    const int a_kb  = (lane >> 4) * 16;
    const int b_row = (lane >> 4) * 8 + (lane & 7);
    const int b_kb  = ((lane >> 3) & 1) * 16;

    float c[2][4][4];
    #pragma unroll
    for (int i = 0; i < 2; i++)
        #pragma unroll
        for (int j = 0; j < 4; j++)
            #pragma unroll
            for (int k = 0; k < 4; k++) c[i][j][k] = 0.f;

    const int nk = K >> 5;
    // prologue: stages 0,1
    load_stage(smb, Ahi, Alo, Bhi, Blo, row0, col0, K, 0, M, tid);
    load_stage(smb + STAGE, Ahi, Alo, Bhi, Blo, row0, col0, K, 32, M, tid);

    int buf = 0;
    for (int it = 0; it < nk; it++) {
        CPA_WAIT1();
        __syncthreads();
        if (it + 2 < nk) {
            int nb = buf + 2; if (nb >= NSTG) nb -= NSTG;
            load_stage(smb + (uint32_t)nb * STAGE, Ahi, Alo, Bhi, Blo,
                       row0, col0, K, (it + 2) << 5, M, tid);
        }
        uint32_t sb = smb + (uint32_t)buf * STAGE;
        #pragma unroll
        for (int kk = 0; kk < 2; kk++) {
            uint32_t bh[8], bl[8];
            #pragma unroll
            for (int nip = 0; nip < 2; nip++) {
                uint32_t baddr = sb + BH_OFF + (wn * 32 + nip * 16 + b_row) * RS + b_kb + kk * 32;
                LDM4(&bh[nip * 4], baddr);
                LDM4(&bl[nip * 4], baddr + (BL_OFF - BH_OFF));
            }
            #pragma unroll
            for (int mi = 0; mi < 2; mi++) {
                uint32_t ah[4], al[4];
                uint32_t aaddr = sb + AH_OFF + (wm * 32 + mi * 16 + a_row) * RS + a_kb + kk * 32;
                LDM4(ah, aaddr);
                LDM4(al, aaddr + (AL_OFF - AH_OFF));
                #pragma unroll
                for (int ni = 0; ni < 4; ni++) {
                    uint32_t b0h = bh[(ni >> 1) * 4 + (ni & 1) * 2];
                    uint32_t b1h = bh[(ni >> 1) * 4 + (ni & 1) * 2 + 1];
                    uint32_t b0l = bl[(ni >> 1) * 4 + (ni & 1) * 2];
                    uint32_t b1l = bl[(ni >> 1) * 4 + (ni & 1) * 2 + 1];
                    MMA_BF16(c[mi][ni], ah, b0h, b1h);
                    MMA_BF16(c[mi][ni], ah, b0l, b1l);
                    MMA_BF16(c[mi][ni], al, b0h, b1h);
                }
            }
        }
        buf++; if (buf >= NSTG) buf = 0;
    }

    // ---- epilogue ----
    const int g = lane >> 2, t = lane & 3;
    #pragma unroll
    for (int mi = 0; mi < 2; mi++) {
        #pragma unroll
        for (int ni = 0; ni < 4; ni++) {
            int col = col0 + wn * 32 + ni * 8 + t * 2;
            float2 bb = bias ? *(const float2*)(bias + col) : make_float2(0.f, 0.f);
            #pragma unroll
            for (int half = 0; half < 2; half++) {
                int gm = row0 + wm * 32 + mi * 16 + g + half * 8;
                if (gm >= M) continue;
                float v0 = c[mi][ni][half * 2 + 0] + bb.x;
                float v1 = c[mi][ni][half * 2 + 1] + bb.y;
                if (act) {
                    v0 = 0.5f * v0 * (1.f + erff(v0 * 0.70710678118f));
                    v1 = 0.5f * v1 * (1.f + erff(v1 * 0.70710678118f));
                }
                if (res) {
                    float2 rv = *(const float2*)(res + (size_t)gm * N + col);
                    v0 += rv.x; v1 += rv.y;
                }
                size_t o = (size_t)gm * N + col;
                if (Chi) {
                    unsigned short h0, l0, h1, l1;
                    split1(v0, h0, l0);
                    split1(v1, h1, l1);
                    *(uint32_t*)(Chi + o) = (uint32_t)h0 | ((uint32_t)h1 << 16);
                    *(uint32_t*)(Clo + o) = (uint32_t)l0 | ((uint32_t)l1 << 16);
                } else {
                    *(float2*)(C + o) = make_float2(v0, v1);
                }
            }
        }
    }
}

// ---------------- patch extraction -> bf16 hi/lo ----------------
__global__ void patch_kernel(const float* __restrict__ x,
        unsigned short* __restrict__ Phi, unsigned short* __restrict__ Plo) {
    int idx = blockIdx.x * blockDim.x + threadIdx.x;
    if (idx >= 1568 * 768) return;
    int m = idx / 768, kcol = idx % 768;
    int t = m / 196, n = m % 196;
    int hp = n / 14, wp = n % 14;
    int c = kcol / 256, rem = kcol % 256;
    int ii = rem / 16, jj = rem % 16;
    float v = x[((t * 3 + c) * 224 + hp * 16 + ii) * 224 + wp * 16 + jj];
    split1(v, Phi[idx], Plo[idx]);
}

// ---------------- assemble h ----------------
__global__ void assemble_kernel(const float* __restrict__ emb, const float* __restrict__ cls,
                                const float* __restrict__ pos, float* __restrict__ h) {
    int idx = blockIdx.x * blockDim.x + threadIdx.x;
    if (idx >= SEQ * DIM) return;
    int m = idx / DIM, dd = idx % DIM;
    int t = m / NTOK, r = m % NTOK;
    float v;
    if (r == 0) {
        v = cls[dd] + pos[dd];
    } else {
        int pp = r - 1;
        int f = pp * DIM + dd;
        int n = f % NPAT, dc = f / NPAT;
        v = emb[(t * NPAT + n) * DIM + dc] + pos[(1 + pp) * DIM + dd];
    }
    h[idx] = v;
}

// ---------------- block reduction ----------------
__device__ __forceinline__ float block_sum256(float v, float* sh) {
    #pragma unroll
    for (int o = 16; o; o >>= 1) v += __shfl_xor_sync(0xffffffffu, v, o);
    if ((threadIdx.x & 31) == 0) sh[threadIdx.x >> 5] = v;
    __syncthreads();
    float t = 0.f;
    #pragma unroll
    for (int i = 0; i < 8; i++) t += sh[i];
    __syncthreads();
    return t;
}

// ---------------- LayerNorm -> bf16 hi/lo ----------------
__global__ void ln_split_kernel(const float* __restrict__ x, const float* __restrict__ g,
        const float* __restrict__ b, unsigned short* __restrict__ yhi,
        unsigned short* __restrict__ ylo) {
    __shared__ float sh[8];
    int row = blockIdx.x, tid = threadIdx.x;
    const float* xr = x + (size_t)row * DIM;
    float v0 = xr[tid], v1 = xr[tid + 256], v2 = xr[tid + 512];
    float mean = block_sum256(v0 + v1 + v2, sh) * (1.f / DIM);
    float d0 = v0 - mean, d1 = v1 - mean, d2 = v2 - mean;
    float var = block_sum256(d0 * d0 + d1 * d1 + d2 * d2, sh) * (1.f / DIM);
    float inv = rsqrtf(var + 1e-5f);
    size_t o = (size_t)row * DIM + tid;
    float y0 = d0 * inv * g[tid]       + b[tid];
    float y1 = d1 * inv * g[tid + 256] + b[tid + 256];
    float y2 = d2 * inv * g[tid + 512] + b[tid + 512];
    split1(y0, yhi[o],       ylo[o]);
    split1(y1, yhi[o + 256], ylo[o + 256]);
    split1(y2, yhi[o + 512], ylo[o + 512]);
}

// ---------------- final LayerNorm (fp32 out) ----------------
__global__ void ln_kernel(const float* __restrict__ x, const float* __restrict__ g,
                          const float* __restrict__ b, float* __restrict__ y) {
    __shared__ float sh[8];
    int row = blockIdx.x, tid = threadIdx.x;
    const float* xr = x + (size_t)row * DIM;
    float v0 = xr[tid], v1 = xr[tid + 256], v2 = xr[tid + 512];
    float mean = block_sum256(v0 + v1 + v2, sh) * (1.f / DIM);
    float d0 = v0 - mean, d1 = v1 - mean, d2 = v2 - mean;
    float var = block_sum256(d0 * d0 + d1 * d1 + d2 * d2, sh) * (1.f / DIM);
    float inv = rsqrtf(var + 1e-5f);
    float* yr = y + (size_t)row * DIM;
    yr[tid]       = d0 * inv * g[tid]       + b[tid];
    yr[tid + 256] = d1 * inv * g[tid + 256] + b[tid + 256];
    yr[tid + 512] = d2 * inv * g[tid + 512] + b[tid + 512];
}

// ---------------- temporal v-mean ----------------
__global__ void vmean_kernel(const float* __restrict__ qkv, float* __restrict__ vmean) {
    int ht = blockIdx.x;
    int t = ht % TFR, h = ht / TFR;
    int d = threadIdx.x;
    float s = 0.f;
    for (int n = 0; n < NTOK; n++)
        s += qkv[(size_t)(t * NTOK + n) * QKVD + 2 * DIM + h * HD + d];
    vmean[ht * HD + d] = s * (1.f / NTOK);
}

// ---------------- attention -> bf16 hi/lo output ----------------
__global__ void attn_kernel(const float* __restrict__ qkv, const float* __restrict__ vmean,
        unsigned short* __restrict__ ohi, unsigned short* __restrict__ olo,
        int keyLen, int numSeg) {
    extern __shared__ float smf[];
    float* qs  = smf;
    float* sc  = smf + QB * HD;
    float* red = sc + QB * keyLen;
    __shared__ float wsum[QB];
    int tid = threadIdx.x;
    int hseg = blockIdx.y;
    int h = hseg / numSeg, seg = hseg % numSeg;
    int base = seg * keyLen;
    int q0 = blockIdx.x * QB;
    int nq = min(QB, keyLen - q0);

    for (int i = tid; i < nq * HD; i += 256) {
        int qi = i / HD, d = i % HD;
        qs[qi * HD + d] = qkv[(size_t)(base + q0 + qi) * QKVD + h * HD + d];
    }
    __syncthreads();

    for (int kk = tid; kk < keyLen; kk += 256) {
        const float4* kp = (const float4*)(qkv + (size_t)(base + kk) * QKVD + DIM + h * HD);
        float4 k4[16];
        #pragma unroll
        for (int j = 0; j < 16; j++) k4[j] = kp[j];
        for (int qi = 0; qi < nq; qi++) {
            const float4* q4p = (const float4*)(qs + qi * HD);
            float s = 0.f;
            #pragma unroll
            for (int j = 0; j < 16; j++) {
                float4 q4 = q4p[j];
                s += q4.x * k4[j].x + q4.y * k4[j].y + q4.z * k4[j].z + q4.w * k4[j].w;
            }
            sc[qi * keyLen + kk] = s * ASCALE;
        }
    }
    __syncthreads();

    int w = tid >> 5, lane = tid & 31;
    if (w < nq) {
        float mx = -1e30f;
        for (int kk = lane; kk < keyLen; kk += 32) mx = fmaxf(mx, sc[w * keyLen + kk]);
        #pragma unroll
        for (int off = 16; off; off >>= 1) mx = fmaxf(mx, __shfl_xor_sync(0xffffffffu, mx, off));
        float sum = 0.f;
        for (int kk = lane; kk < keyLen; kk += 32) {
            float e = __expf(sc[w * keyLen + kk] - mx);
            sc[w * keyLen + kk] = e;
            sum += e;
        }
        #pragma unroll
        for (int off = 16; off; off >>= 1) sum += __shfl_xor_sync(0xffffffffu, sum, off);
        if (lane == 0) wsum[w] = sum;
    }
    __syncthreads();

    int d = tid & 63, part = tid >> 6;
    float acc[QB];
    #pragma unroll
    for (int qi = 0; qi < QB; qi++) acc[qi] = 0.f;
    for (int kk = part; kk < keyLen; kk += 4) {
        float v = qkv[(size_t)(base + kk) * QKVD + 2 * DIM + h * HD + d];
        #pragma unroll
        for (int qi = 0; qi < QB; qi++)
            if (qi < nq) acc[qi] += sc[qi * keyLen + kk] * v;
    }
    #pragma unroll
    for (int qi = 0; qi < QB; qi++)
        red[(part * QB + qi) * HD + d] = acc[qi];
    __syncthreads();
    if (part == 0) {
        for (int qi = 0; qi < nq; qi++) {
            float s = red[qi * HD + d] + red[(QB + qi) * HD + d]
                    + red[(2 * QB + qi) * HD + d] + red[(3 * QB + qi) * HD + d];
            s /= wsum[qi];
            if (vmean) s += vmean[hseg * HD + d];
            size_t o = (size_t)(base + q0 + qi) * DIM + h * HD + d;
            split1(s, ohi[o], olo[o]);
        }
    }
}

// ---------------- host ----------------
static void run_mma(const unsigned short* Ahi, const unsigned short* Alo,
                    const unsigned short* Bhi, const unsigned short* Blo,
                    const float* bias, const float* res, float* C,
                    unsigned short* Chi, unsigned short* Clo,
                    int M, int N, int K, int act) {
    dim3 grid(N / 128, (M + 63) / 64);
    mma_gemm<<<grid, 256, NSTG * STAGE>>>(Ahi, Alo, Bhi, Blo, bias, res, C, Chi, Clo, M, N, K, act);
}

extern "C" void kernel_launch(void* const* d_in, const int* in_sizes, int n_in,
                              void* d_out, int out_size) {
    const float* x       = (const float*)d_in[0];
    const float* W_patch = (const float*)d_in[1];
    const float* b_patch = (const float*)d_in[2];
    const float* cls     = (const float*)d_in[3];
    const float* pos     = (const float*)d_in[4];
    const float* ln1_g   = (const float*)d_in[5];
    const float* ln1_b   = (const float*)d_in[6];
    const float* qkv_w   = (const float*)d_in[7];
    const float* qkv_b   = (const float*)d_in[8];
    const float* proj_w  = (const float*)d_in[9];
    const float* proj_b  = (const float*)d_in[10];
    const float* ln2_g   = (const float*)d_in[11];
    const float* ln2_b   = (const float*)d_in[12];
    const float* fc1_w   = (const float*)d_in[13];
    const float* fc1_b   = (const float*)d_in[14];
    const float* fc2_w   = (const float*)d_in[15];
    const float* fc2_b   = (const float*)d_in[16];
    const float* lnf_g   = (const float*)d_in[17];
    const float* lnf_b   = (const float*)d_in[18];

    float *emb_, *h_, *qkv_, *vm_;
    unsigned short *pH, *pL, *aH, *aL, *oH, *oL, *mH, *mL;
    unsigned short *wpH, *wpL, *qkH, *qkL, *prH, *prL, *f1H, *f1L, *f2H, *f2L;
    cudaGetSymbolAddress((void**)&emb_, g_emb);
    cudaGetSymbolAddress((void**)&h_,   g_h);
    cudaGetSymbolAddress((void**)&qkv_, g_qkv);
    cudaGetSymbolAddress((void**)&vm_,  g_vmean);
    cudaGetSymbolAddress((void**)&pH, g_p_hi);   cudaGetSymbolAddress((void**)&pL, g_p_lo);
    cudaGetSymbolAddress((void**)&aH, g_a_hi);   cudaGetSymbolAddress((void**)&aL, g_a_lo);
    cudaGetSymbolAddress((void**)&oH, g_o_hi);   cudaGetSymbolAddress((void**)&oL, g_o_lo);
    cudaGetSymbolAddress((void**)&mH, g_m_hi);   cudaGetSymbolAddress((void**)&mL, g_m_lo);
    cudaGetSymbolAddress((void**)&wpH, g_wp_hi); cudaGetSymbolAddress((void**)&wpL, g_wp_lo);
    cudaGetSymbolAddress((void**)&qkH, g_qkvT_hi); cudaGetSymbolAddress((void**)&qkL, g_qkvT_lo);
    cudaGetSymbolAddress((void**)&prH, g_projT_hi); cudaGetSymbolAddress((void**)&prL, g_projT_lo);
    cudaGetSymbolAddress((void**)&f1H, g_fc1T_hi); cudaGetSymbolAddress((void**)&f1L, g_fc1T_lo);
    cudaGetSymbolAddress((void**)&f2H, g_fc2T_hi); cudaGetSymbolAddress((void**)&f2L, g_fc2T_lo);

    cudaFuncSetAttribute(mma_gemm, cudaFuncAttributeMaxDynamicSharedMemorySize, NSTG * STAGE);

    size_t smem_joint = (size_t)(QB * HD + QB * SEQ  + 4 * QB * HD) * sizeof(float);
    size_t smem_sp    = (size_t)(QB * HD + QB * NTOK + 4 * QB * HD) * sizeof(float);
    cudaFuncSetAttribute(attn_kernel, cudaFuncAttributeMaxDynamicSharedMemorySize, (int)smem_joint);

    // weights -> bf16 hi/lo [N,K]
    dim3 tb(32, 8);
    transpose_split_kernel<<<dim3(QKVD / 32, DIM / 32, 12), tb>>>(qkv_w,  qkH, qkL, DIM, QKVD);
    transpose_split_kernel<<<dim3(DIM / 32,  DIM / 32, 12), tb>>>(proj_w, prH, prL, DIM, DIM);
    transpose_split_kernel<<<dim3(MLPD / 32, DIM / 32, 12), tb>>>(fc1_w,  f1H, f1L, DIM, MLPD);
    transpose_split_kernel<<<dim3(DIM / 32, MLPD / 32, 12), tb>>>(fc2_w,  f2H, f2L, MLPD, DIM);
    split_kernel<<<(DIM * DIM + 255) / 256, 256>>>(W_patch, wpH, wpL, DIM * DIM);

    // patch embed + assembly
    patch_kernel<<<(1568 * 768 + 255) / 256, 256>>>(x, pH, pL);
    run_mma(pH, pL, wpH, wpL, b_patch, nullptr, emb_, nullptr, nullptr, 1568, 768, 768, 0);
    assemble_kernel<<<(SEQ * DIM + 255) / 256, 256>>>(emb_, cls, pos, h_);

    for (int i = 0; i < 12; i++) {
        ln_split_kernel<<<SEQ, 256>>>(h_, ln1_g + i * DIM, ln1_b + i * DIM, aH, aL);
        run_mma(aH, aL, qkH + (size_t)i * QKVD * DIM, qkL + (size_t)i * QKVD * DIM,
                qkv_b + i * QKVD, nullptr, qkv_, nullptr, nullptr, SEQ, QKVD, DIM, 0);
        if ((i & 1) == 0) {
            vmean_kernel<<<NHEAD * TFR, HD>>>(qkv_, vm_);
            dim3 g((NTOK + QB - 1) / QB, NHEAD * TFR);
            attn_kernel<<<g, 256, smem_sp>>>(qkv_, vm_, oH, oL, NTOK, TFR);
        } else {
            dim3 g(SEQ / QB, NHEAD);
            attn_kernel<<<g, 256, smem_joint>>>(qkv_, nullptr, oH, oL, SEQ, 1);
        }
        run_mma(oH, oL, prH + (size_t)i * DIM * DIM, prL + (size_t)i * DIM * DIM,
                proj_b + i * DIM, h_, h_, nullptr, nullptr, SEQ, DIM, DIM, 0);
        ln_split_kernel<<<SEQ, 256>>>(h_, ln2_g + i * DIM, ln2_b + i * DIM, aH, aL);
        run_mma(aH, aL, f1H + (size_t)i * MLPD * DIM, f1L + (size_t)i * MLPD * DIM,
                fc1_b + i * MLPD, nullptr, nullptr, mH, mL, SEQ, MLPD, DIM, 1);
        run_mma(mH, mL, f2H + (size_t)i * DIM * MLPD, f2L + (size_t)i * DIM * MLPD,
                fc2_b + i * DIM, h_, h_, nullptr, nullptr, SEQ, DIM, MLPD, 0);
    }

    ln_kernel<<<SEQ, 256>>>(h_, lnf_g, lnf_b, (float*)d_out);
}